// round 3
// baseline (speedup 1.0000x reference)
#include <cuda_runtime.h>
#include <cuda_bf16.h>

#define FULL 0xFFFFFFFFu

constexpr int BATCH = 4096;
constexpr int DIM   = 32;
constexpr int N_MEM = 32;
constexpr int N_HOP = 2;
constexpr int BPB   = 4;    // batch elements per block (2 warps each -> 8 warps)
constexpr int PSTR  = 33;   // padded row stride for partial matrix

__global__ void __launch_bounds__(256) ripple_kernel(
    const int* __restrict__ items,
    const int* __restrict__ mem_h,
    const int* __restrict__ mem_r,
    const int* __restrict__ mem_t,
    const int* __restrict__ users,
    const float* __restrict__ entity,
    const float* __restrict__ relation,
    const float* __restrict__ user_table,
    const float* __restrict__ W,
    float* __restrict__ out)
{
    __shared__ float Wt[DIM * DIM];           // W transposed
    __shared__ float P[BPB][N_MEM * PSTR];    // per-batch-elem partial matrix
    __shared__ float O[BPB][2][DIM];          // per-half o partials

    const int tid = threadIdx.x;
    for (int i = tid; i < DIM * DIM; i += blockDim.x) {
        int d = i >> 5, e = i & 31;
        Wt[e * DIM + d] = W[i];
    }
    __syncthreads();

    const int lane = tid & 31;
    const int warp = tid >> 5;
    const int pair = warp >> 1;      // 0..3 : which batch element in block
    const int half = warp & 1;       // 0/1  : which 16 memories this warp owns
    const int b = blockIdx.x * BPB + pair;

    const int g = lane >> 3;   // row-group 0..3 (d = 4k + g)
    const int c = lane & 7;    // float4 col-group (e = 4c..4c+3)

    float* __restrict__ Pb = P[pair];

    // item[lane] — one dim per lane (both warps of the pair hold it)
    float item = entity[items[b] * DIM + lane];
    float y = 0.f;

    #pragma unroll
    for (int hop = 0; hop < N_HOP; ++hop) {
        const int base = hop * BATCH * N_MEM + b * N_MEM;
        const int hidx = mem_h[base + lane];   // lane m holds memory m's indices
        const int ridx = mem_r[base + lane];
        const int tidx = mem_t[base + lane];

        // ---- partials for this warp's 16 memories ----
        #pragma unroll 4
        for (int mm = 0; mm < 16; ++mm) {
            const int m = half * 16 + mm;
            const int r_i = __shfl_sync(FULL, ridx, m);
            const int h_i = __shfl_sync(FULL, hidx, m);
            const float4* __restrict__ R4 =
                (const float4*)(relation + r_i * (DIM * DIM));

            float4 acc = make_float4(0.f, 0.f, 0.f, 0.f);
            #pragma unroll
            for (int k = 0; k < 8; ++k) {
                const int d = 4 * k + g;
                const float4 r4 = R4[d * 8 + c];
                const float it = __shfl_sync(FULL, item, d);
                acc.x = fmaf(it, r4.x, acc.x);
                acc.y = fmaf(it, r4.y, acc.y);
                acc.z = fmaf(it, r4.z, acc.z);
                acc.w = fmaf(it, r4.w, acc.w);
            }
            const float4 h4 = ((const float4*)(entity + h_i * DIM))[c];
            Pb[m * PSTR + lane] =
                acc.x * h4.x + acc.y * h4.y + acc.z * h4.z + acc.w * h4.w;
        }
        __syncthreads();   // partials visible to both warps of every pair

        // ---- logit[m] = row-sum of P[m][*] (lane m owns memory m; both warps) ----
        float logit = 0.f;
        {
            const float* __restrict__ row = &Pb[lane * PSTR];
            #pragma unroll
            for (int j = 0; j < 32; ++j) logit += row[j];
        }

        // ---- softmax over 32 memories (redundant in both warps, consistent) ----
        float mx = logit;
        #pragma unroll
        for (int off = 16; off; off >>= 1)
            mx = fmaxf(mx, __shfl_xor_sync(FULL, mx, off));
        const float ex = __expf(logit - mx);
        float denom = ex;
        #pragma unroll
        for (int off = 16; off; off >>= 1)
            denom += __shfl_xor_sync(FULL, denom, off);
        const float prob = ex / denom;

        // ---- o[d]: this warp accumulates its 16 memories ----
        float oh = 0.f;
        #pragma unroll 4
        for (int mm = 0; mm < 16; ++mm) {
            const int m = half * 16 + mm;
            const int t_i = __shfl_sync(FULL, tidx, m);
            const float p = __shfl_sync(FULL, prob, m);
            oh = fmaf(p, entity[t_i * DIM + lane], oh);
        }
        O[pair][half][lane] = oh;
        __syncthreads();   // also orders P reads above before next hop's P writes
        const float o = O[pair][0][lane] + O[pair][1][lane];
        y += o;

        // ---- item = (item + o) @ W^T via transposed-W smem (redundant) ----
        const float tmp = item + o;
        float accw = 0.f;
        #pragma unroll
        for (int e = 0; e < DIM; ++e)
            accw = fmaf(__shfl_sync(FULL, tmp, e), Wt[e * DIM + lane], accw);
        item = accw;
    }

    // ---- score = sigmoid(item . (o0 + o1 + user_emb)) ----
    y += user_table[users[b] * DIM + lane];
    float s = item * y;
    #pragma unroll
    for (int off = 16; off; off >>= 1)
        s += __shfl_xor_sync(FULL, s, off);
    if (half == 0 && lane == 0)
        out[b] = 1.f / (1.f + __expf(-s));
}

extern "C" void kernel_launch(void* const* d_in, const int* in_sizes, int n_in,
                              void* d_out, int out_size) {
    const int*   items     = (const int*)d_in[0];
    const int*   mem_h     = (const int*)d_in[2];
    const int*   mem_r     = (const int*)d_in[3];
    const int*   mem_t     = (const int*)d_in[4];
    const int*   users     = (const int*)d_in[5];
    const float* entity    = (const float*)d_in[6];
    const float* relation  = (const float*)d_in[7];
    const float* user_tab  = (const float*)d_in[8];
    const float* W         = (const float*)d_in[9];
    float* out = (float*)d_out;

    ripple_kernel<<<BATCH / BPB, 256>>>(items, mem_h, mem_r, mem_t, users,
                                        entity, relation, user_tab, W, out);
}

// round 4
// speedup vs baseline: 1.2548x; 1.2548x over previous
#include <cuda_runtime.h>
#include <cuda_bf16.h>

#define FULL 0xFFFFFFFFu

constexpr int BATCH = 4096;
constexpr int DIM   = 32;
constexpr int N_MEM = 32;
constexpr int N_HOP = 2;
constexpr int N_REL = 64;
constexpr int PSTR  = 33;

// Static scratch (no allocations allowed).
__device__ __nv_bfloat16 g_rel[N_REL * DIM * DIM];   // 128 KB bf16 relation copy
__device__ float g_Wt[DIM * DIM];                    // transposed transform

__global__ void prep_kernel(const float* __restrict__ rel,
                            const float* __restrict__ W) {
    const int i = blockIdx.x * blockDim.x + threadIdx.x;
    if (i < N_REL * DIM * DIM) g_rel[i] = __float2bfloat16(rel[i]);
    if (i < DIM * DIM) {
        const int d = i >> 5, e = i & 31;
        g_Wt[e * DIM + d] = W[i];
    }
}

// bf16 pair (packed in u32) -> two exact fp32 (bf16 is fp32's top half)
__device__ __forceinline__ float bf_lo(unsigned u) { return __uint_as_float(u << 16); }
__device__ __forceinline__ float bf_hi(unsigned u) { return __uint_as_float(u & 0xFFFF0000u); }

__global__ void __launch_bounds__(64, 20) ripple_kernel(
    const int* __restrict__ items,
    const int* __restrict__ mem_h,
    const int* __restrict__ mem_r,
    const int* __restrict__ mem_t,
    const int* __restrict__ users,
    const float* __restrict__ entity,
    const float* __restrict__ user_table,
    float* __restrict__ out)
{
    __shared__ float P[N_MEM * PSTR];   // partial matrix for this batch element
    __shared__ float O[2][DIM];         // per-half o partials

    const int tid  = threadIdx.x;
    const int lane = tid & 31;
    const int half = tid >> 5;          // which 16 memories this warp owns
    const int b    = blockIdx.x;

    const int c2 = lane & 3;            // e-octet: e = 8*c2 .. 8*c2+7
    const int g2 = lane >> 2;           // row group: d = g2 + 8k, k=0..3

    float item = entity[items[b] * DIM + lane];
    float y = 0.f;

    #pragma unroll
    for (int hop = 0; hop < N_HOP; ++hop) {
        const int base = hop * BATCH * N_MEM + b * N_MEM;
        const int hidx = mem_h[base + lane];   // lane m holds memory m's indices
        const int ridx = mem_r[base + lane];
        const int tidx = mem_t[base + lane];

        // ---- partials for this warp's 16 memories ----
        #pragma unroll 2
        for (int mm = 0; mm < 16; ++mm) {
            const int m  = half * 16 + mm;
            const int r_i = __shfl_sync(FULL, ridx, m);
            const int h_i = __shfl_sync(FULL, hidx, m);
            // bf16 row = 64 B = 4 uint4; lane's chunk: rows g2+8k, octet c2
            const uint4* __restrict__ R4 =
                (const uint4*)(g_rel + r_i * (DIM * DIM));

            float a0=0.f,a1=0.f,a2=0.f,a3=0.f,a4=0.f,a5=0.f,a6=0.f,a7=0.f;
            #pragma unroll
            for (int k = 0; k < 4; ++k) {
                const int d = g2 + 8 * k;
                const uint4 q = R4[d * 4 + c2];
                const float it = __shfl_sync(FULL, item, d);
                a0 = fmaf(it, bf_lo(q.x), a0);
                a1 = fmaf(it, bf_hi(q.x), a1);
                a2 = fmaf(it, bf_lo(q.y), a2);
                a3 = fmaf(it, bf_hi(q.y), a3);
                a4 = fmaf(it, bf_lo(q.z), a4);
                a5 = fmaf(it, bf_hi(q.z), a5);
                a6 = fmaf(it, bf_lo(q.w), a6);
                a7 = fmaf(it, bf_hi(q.w), a7);
            }
            const float4 ha = *(const float4*)(entity + h_i * DIM + 8 * c2);
            const float4 hb = *(const float4*)(entity + h_i * DIM + 8 * c2 + 4);
            P[m * PSTR + lane] =
                a0*ha.x + a1*ha.y + a2*ha.z + a3*ha.w +
                a4*hb.x + a5*hb.y + a6*hb.z + a7*hb.w;
        }
        __syncthreads();   // partials visible to both warps

        // ---- logit[m] = row-sum of P[m][*] (lane m owns memory m) ----
        float logit = 0.f;
        {
            const float* __restrict__ row = &P[lane * PSTR];
            #pragma unroll
            for (int j = 0; j < 32; ++j) logit += row[j];
        }

        // ---- softmax over 32 memories (redundant in both warps) ----
        float mx = logit;
        #pragma unroll
        for (int off = 16; off; off >>= 1)
            mx = fmaxf(mx, __shfl_xor_sync(FULL, mx, off));
        const float ex = __expf(logit - mx);
        float denom = ex;
        #pragma unroll
        for (int off = 16; off; off >>= 1)
            denom += __shfl_xor_sync(FULL, denom, off);
        const float prob = ex / denom;

        // ---- o[d]: this warp accumulates its 16 memories (lane = d) ----
        float oh = 0.f;
        #pragma unroll 4
        for (int mm = 0; mm < 16; ++mm) {
            const int m  = half * 16 + mm;
            const int t_i = __shfl_sync(FULL, tidx, m);
            const float p = __shfl_sync(FULL, prob, m);
            oh = fmaf(p, entity[t_i * DIM + lane], oh);
        }
        O[half][lane] = oh;
        __syncthreads();   // also orders P reads before next hop's P writes
        const float o = O[0][lane] + O[1][lane];
        y += o;

        // ---- item = (item + o) @ W^T via pre-transposed W (L1-resident) ----
        const float tmp = item + o;
        float accw = 0.f;
        #pragma unroll
        for (int e = 0; e < DIM; ++e)
            accw = fmaf(__shfl_sync(FULL, tmp, e), g_Wt[e * DIM + lane], accw);
        item = accw;
    }

    // ---- score = sigmoid(item . (o0 + o1 + user_emb)) ----
    y += user_table[users[b] * DIM + lane];
    float s = item * y;
    #pragma unroll
    for (int off = 16; off; off >>= 1)
        s += __shfl_xor_sync(FULL, s, off);
    if (half == 0 && lane == 0)
        out[b] = 1.f / (1.f + __expf(-s));
}

extern "C" void kernel_launch(void* const* d_in, const int* in_sizes, int n_in,
                              void* d_out, int out_size) {
    const int*   items     = (const int*)d_in[0];
    const int*   mem_h     = (const int*)d_in[2];
    const int*   mem_r     = (const int*)d_in[3];
    const int*   mem_t     = (const int*)d_in[4];
    const int*   users     = (const int*)d_in[5];
    const float* entity    = (const float*)d_in[6];
    const float* relation  = (const float*)d_in[7];
    const float* user_tab  = (const float*)d_in[8];
    const float* W         = (const float*)d_in[9];
    float* out = (float*)d_out;

    const int prep_elems = N_REL * DIM * DIM;
    prep_kernel<<<(prep_elems + 255) / 256, 256>>>(relation, W);
    ripple_kernel<<<BATCH, 64>>>(items, mem_h, mem_r, mem_t, users,
                                 entity, user_tab, out);
}

// round 5
// speedup vs baseline: 1.6671x; 1.3286x over previous
#include <cuda_runtime.h>
#include <cuda_bf16.h>

#define FULL 0xFFFFFFFFu

constexpr int BATCH = 4096;
constexpr int DIM   = 32;
constexpr int N_MEM = 32;
constexpr int N_REL = 64;
constexpr int NCOL  = N_REL * DIM;   // 2048

// Static scratch (no runtime allocation allowed).
__device__ float          g_U[BATCH * NCOL];          // 32 MB: U[b][r*32+e]
__device__ float          g_item[BATCH * DIM];        // fp32 item state
__device__ __nv_bfloat16  g_item_bf[BATCH * DIM];     // bf16 copy (GEMM A)
__device__ __nv_bfloat16  g_Bt[NCOL * DIM];           // Bt[n][k] = R_r[k][e], n=r*32+e
__device__ float          g_Wt[DIM * DIM];            // W transposed
__device__ float          g_y[BATCH * DIM];           // o accumulator

// ---------------------------------------------------------------- prep
__global__ void prep_kernel(const int* __restrict__ items,
                            const float* __restrict__ entity,
                            const float* __restrict__ relation,
                            const float* __restrict__ W) {
    const int i = blockIdx.x * blockDim.x + threadIdx.x;
    if (i < BATCH * DIM) {
        const int b = i >> 5, e = i & 31;
        const float v = entity[items[b] * DIM + e];
        g_item[i] = v;
        g_item_bf[i] = __float2bfloat16(v);
    }
    if (i < NCOL * DIM) {
        const int n = i >> 5, k = i & 31;       // g_Bt[n*32+k]
        const int r = n >> 5, e = n & 31;
        g_Bt[i] = __float2bfloat16(relation[r * 1024 + k * DIM + e]);
    }
    if (i < DIM * DIM) {
        const int d = i >> 5, e = i & 31;
        g_Wt[e * DIM + d] = W[i];
    }
}

// ---------------------------------------------------------------- GEMM
// U = A(4096x32, bf16 row-major) * B(32x2048), B given as Bt[n][k] (col-major B).
// mma.sync.m16n8k16 row.col bf16->fp32. No smem: A/B rows are 64B, L1-hot.
__device__ __forceinline__ void mma16816(float c[4], const unsigned a[4],
                                         const unsigned b[2]) {
    asm volatile(
        "mma.sync.aligned.m16n8k16.row.col.f32.bf16.bf16.f32 "
        "{%0,%1,%2,%3}, {%4,%5,%6,%7}, {%8,%9}, {%0,%1,%2,%3};\n"
        : "+f"(c[0]), "+f"(c[1]), "+f"(c[2]), "+f"(c[3])
        : "r"(a[0]), "r"(a[1]), "r"(a[2]), "r"(a[3]),
          "r"(b[0]), "r"(b[1]));
}

__global__ void __launch_bounds__(256) gemm_kernel() {
    const int warp = threadIdx.x >> 5;
    const int lane = threadIdx.x & 31;
    const int m0 = blockIdx.y * 128 + warp * 16;   // 8 warps stacked on M
    const int n0 = blockIdx.x * 64;

    const unsigned* __restrict__ pA = (const unsigned*)g_item_bf;  // [4096][16] u32
    const unsigned* __restrict__ pB = (const unsigned*)g_Bt;       // [2048][16] u32

    // A fragments for k=0..31 (two m16k16 frags), row-major layout:
    // a[j]: (row l/4 (+8), colpair l%4 (+4 for k+8))
    const int ra = (m0 + (lane >> 2)) * 16 + (lane & 3);
    unsigned a[8];
    a[0] = pA[ra];       a[1] = pA[ra + 128];
    a[2] = pA[ra + 4];   a[3] = pA[ra + 132];
    a[4] = pA[ra + 8];   a[5] = pA[ra + 136];
    a[6] = pA[ra + 12];  a[7] = pA[ra + 140];

    #pragma unroll
    for (int j = 0; j < 8; ++j) {                  // 8 n-steps of 8 cols
        const int rb = (n0 + 8 * j + (lane >> 2)) * 16 + (lane & 3);
        const unsigned b0[2] = { pB[rb],     pB[rb + 4]  };   // k 0-15
        const unsigned b1[2] = { pB[rb + 8], pB[rb + 12] };   // k 16-31
        float c[4] = {0.f, 0.f, 0.f, 0.f};
        mma16816(c, a,     b0);
        mma16816(c, a + 4, b1);

        float* __restrict__ Up =
            g_U + (m0 + (lane >> 2)) * NCOL + n0 + 8 * j + 2 * (lane & 3);
        *(float2*)Up                 = make_float2(c[0], c[1]);
        *(float2*)(Up + 8 * NCOL)    = make_float2(c[2], c[3]);
    }
}

// ---------------------------------------------------------------- attention
constexpr int AW = 8;   // warps (batch elems) per attn block

__global__ void __launch_bounds__(256) attn_kernel(
    const int* __restrict__ mem_h,
    const int* __restrict__ mem_r,
    const int* __restrict__ mem_t,
    const int* __restrict__ users,
    const float* __restrict__ entity,
    const float* __restrict__ user_table,
    float* __restrict__ out,
    int hop, int last)
{
    __shared__ float P[AW][N_MEM * 9];

    const int lane = threadIdx.x & 31;
    const int warp = threadIdx.x >> 5;
    const int b = blockIdx.x * AW + warp;
    float* __restrict__ Pw = P[warp];

    const int base = hop * BATCH * N_MEM + b * N_MEM;
    const int hidx = mem_h[base + lane];
    const int ridx = mem_r[base + lane];
    const int tidx = mem_t[base + lane];

    const float item = g_item[b * DIM + lane];

    // ---- partial dots: 4 memories per iteration, 8 lanes each ----
    const int mq = lane >> 3;          // which of the 4 memories
    const int c  = lane & 7;           // float4 chunk (e = 4c..4c+3)
    const float* __restrict__ Ub = g_U + b * NCOL;

    #pragma unroll
    for (int it = 0; it < 8; ++it) {
        const int m = it * 4 + mq;
        const int r_i = __shfl_sync(FULL, ridx, m);
        const int h_i = __shfl_sync(FULL, hidx, m);
        const float4 u4 = *(const float4*)(Ub + r_i * DIM + 4 * c);
        const float4 h4 = *(const float4*)(entity + h_i * DIM + 4 * c);
        Pw[m * 9 + c] = u4.x * h4.x + u4.y * h4.y + u4.z * h4.z + u4.w * h4.w;
    }
    __syncwarp();

    // ---- logit[m] (lane m) = sum of 8 partials ----
    float logit = 0.f;
    #pragma unroll
    for (int j = 0; j < 8; ++j) logit += Pw[lane * 9 + j];

    // ---- softmax ----
    float mx = logit;
    #pragma unroll
    for (int off = 16; off; off >>= 1)
        mx = fmaxf(mx, __shfl_xor_sync(FULL, mx, off));
    const float ex = __expf(logit - mx);
    float denom = ex;
    #pragma unroll
    for (int off = 16; off; off >>= 1)
        denom += __shfl_xor_sync(FULL, denom, off);
    const float prob = ex / denom;

    // ---- o[d] = sum_m prob[m] * t_m[d] ----
    float o = 0.f;
    #pragma unroll 4
    for (int m = 0; m < N_MEM; ++m) {
        const int t_i = __shfl_sync(FULL, tidx, m);
        const float p = __shfl_sync(FULL, prob, m);
        o = fmaf(p, entity[t_i * DIM + lane], o);
    }

    // ---- item' = (item + o) @ W^T ----
    const float tmp = item + o;
    float itn = 0.f;
    #pragma unroll
    for (int e = 0; e < DIM; ++e)
        itn = fmaf(__shfl_sync(FULL, tmp, e), g_Wt[e * DIM + lane], itn);

    if (!last) {
        g_item[b * DIM + lane] = itn;
        g_item_bf[b * DIM + lane] = __float2bfloat16(itn);
        g_y[b * DIM + lane] = o;
    } else {
        const float y = g_y[b * DIM + lane] + o
                      + user_table[users[b] * DIM + lane];
        float s = itn * y;
        #pragma unroll
        for (int off = 16; off; off >>= 1)
            s += __shfl_xor_sync(FULL, s, off);
        if (lane == 0)
            out[b] = 1.f / (1.f + __expf(-s));
    }
}

// ---------------------------------------------------------------- launch
extern "C" void kernel_launch(void* const* d_in, const int* in_sizes, int n_in,
                              void* d_out, int out_size) {
    const int*   items     = (const int*)d_in[0];
    const int*   mem_h     = (const int*)d_in[2];
    const int*   mem_r     = (const int*)d_in[3];
    const int*   mem_t     = (const int*)d_in[4];
    const int*   users     = (const int*)d_in[5];
    const float* entity    = (const float*)d_in[6];
    const float* relation  = (const float*)d_in[7];
    const float* user_tab  = (const float*)d_in[8];
    const float* W         = (const float*)d_in[9];
    float* out = (float*)d_out;

    prep_kernel<<<(BATCH * DIM + 255) / 256, 256>>>(items, entity, relation, W);

    const dim3 ggrid(NCOL / 64, BATCH / 128);
    gemm_kernel<<<ggrid, 256>>>();
    attn_kernel<<<BATCH / AW, 256>>>(mem_h, mem_r, mem_t, users,
                                     entity, user_tab, out, 0, 0);
    gemm_kernel<<<ggrid, 256>>>();
    attn_kernel<<<BATCH / AW, 256>>>(mem_h, mem_r, mem_t, users,
                                     entity, user_tab, out, 1, 1);
}

// round 6
// speedup vs baseline: 2.1478x; 1.2883x over previous
#include <cuda_runtime.h>
#include <cuda_bf16.h>

#define FULL 0xFFFFFFFFu

constexpr int BATCH = 4096;
constexpr int DIM   = 32;
constexpr int N_MEM = 32;
constexpr int N_REL = 64;
constexpr int NCOL  = N_REL * DIM;   // 2048

// Static scratch (no runtime allocation allowed).
__device__ __nv_bfloat16  g_U[BATCH * NCOL];          // 16 MB bf16 U[b][r*32+e]
__device__ float          g_item[BATCH * DIM];        // fp32 item state
__device__ __nv_bfloat16  g_item_bf[BATCH * DIM];     // bf16 copy (GEMM A)
__device__ __nv_bfloat16  g_Bt[NCOL * DIM];           // Bt[n][k]=R_r[k][e], n=r*32+e
__device__ float          g_Wt[DIM * DIM];            // W transposed
__device__ float          g_y[BATCH * DIM];           // o accumulator

__device__ __forceinline__ float bf_lo(unsigned u) { return __uint_as_float(u << 16); }
__device__ __forceinline__ float bf_hi(unsigned u) { return __uint_as_float(u & 0xFFFF0000u); }

// ---------------------------------------------------------------- prep
__global__ void prep_kernel(const int* __restrict__ items,
                            const float* __restrict__ entity,
                            const float* __restrict__ relation,
                            const float* __restrict__ W) {
    const int i = blockIdx.x * blockDim.x + threadIdx.x;
    if (i < BATCH * DIM) {
        const int b = i >> 5, e = i & 31;
        const float v = entity[items[b] * DIM + e];
        g_item[i] = v;
        g_item_bf[i] = __float2bfloat16(v);
    }
    if (i < NCOL * DIM) {
        const int n = i >> 5, k = i & 31;
        const int r = n >> 5, e = n & 31;
        g_Bt[i] = __float2bfloat16(relation[r * 1024 + k * DIM + e]);
    }
    if (i < DIM * DIM) {
        const int d = i >> 5, e = i & 31;
        g_Wt[e * DIM + d] = W[i];
    }
}

// ---------------------------------------------------------------- GEMM
// U(4096x2048, bf16) = A(4096x32 bf16 row-major) * B(32x2048), B as Bt[n][k].
__device__ __forceinline__ void mma16816(float c[4], const unsigned* a,
                                         const unsigned* b) {
    asm volatile(
        "mma.sync.aligned.m16n8k16.row.col.f32.bf16.bf16.f32 "
        "{%0,%1,%2,%3}, {%4,%5,%6,%7}, {%8,%9}, {%0,%1,%2,%3};\n"
        : "+f"(c[0]), "+f"(c[1]), "+f"(c[2]), "+f"(c[3])
        : "r"(a[0]), "r"(a[1]), "r"(a[2]), "r"(a[3]),
          "r"(b[0]), "r"(b[1]));
}

__device__ __forceinline__ void ldsm_x4(unsigned& r0, unsigned& r1,
                                        unsigned& r2, unsigned& r3,
                                        unsigned addr) {
    asm volatile(
        "ldmatrix.sync.aligned.m8n8.x4.shared.b16 {%0,%1,%2,%3}, [%4];\n"
        : "=r"(r0), "=r"(r1), "=r"(r2), "=r"(r3) : "r"(addr));
}

constexpr int GM = 128, GN = 64;
constexpr int ASTR = 80;    // bytes per sA row (64 payload + 16 pad)
constexpr int BSTR = 80;    // bytes per sB row
constexpr int OSTR = 144;   // bytes per sO row (128 payload + 16 pad)

__global__ void __launch_bounds__(256) gemm_kernel() {
    __shared__ __align__(16) char sA[GM * ASTR];   // 10 KB
    __shared__ __align__(16) char sB[GN * BSTR];   // 5 KB
    __shared__ __align__(16) char sO[GM * OSTR];   // 18 KB

    const int tid  = threadIdx.x;
    const int lane = tid & 31;
    const int warp = tid >> 5;
    const int m0 = blockIdx.y * GM;
    const int n0 = blockIdx.x * GN;

    // ---- stage A (128 rows x 64 B) and B (64 rows x 64 B), coalesced ----
    {
        const int row = tid >> 1, half = tid & 1;
        const uint4* src = (const uint4*)(g_item_bf + (m0 + row) * DIM) + half * 2;
        uint4* dst = (uint4*)(sA + row * ASTR) + half * 2;
        dst[0] = src[0];
        dst[1] = src[1];
    }
    if (tid < 128) {
        const int row = tid >> 1, half = tid & 1;
        const uint4* src = (const uint4*)(g_Bt + (n0 + row) * DIM) + half * 2;
        uint4* dst = (uint4*)(sB + row * BSTR) + half * 2;
        dst[0] = src[0];
        dst[1] = src[1];
    }
    __syncthreads();

    // ---- A fragments (16 rows per warp, full K=32) via ldmatrix ----
    const unsigned sA32 = (unsigned)__cvta_generic_to_shared(sA);
    const unsigned sB32 = (unsigned)__cvta_generic_to_shared(sB);

    const int mat = lane >> 3, mrow = lane & 7;
    unsigned a[8];
    {
        const unsigned rowa = warp * 16 + mrow + (mat & 1) * 8;
        const unsigned coff = (mat >> 1) * 16;
        ldsm_x4(a[0], a[1], a[2], a[3], sA32 + rowa * ASTR + coff);        // k 0-15
        ldsm_x4(a[4], a[5], a[6], a[7], sA32 + rowa * ASTR + 32 + coff);   // k 16-31
    }

    // ---- per-8-col step: B frags + 2 MMAs + bf16 pack into sO ----
    const unsigned baddr = sB32 + (lane & 7) * BSTR + (lane >> 3) * 16;
    #pragma unroll
    for (int j = 0; j < 8; ++j) {
        unsigned b[4];
        ldsm_x4(b[0], b[1], b[2], b[3], baddr + j * 8 * BSTR);
        float c[4] = {0.f, 0.f, 0.f, 0.f};
        mma16816(c, a, b);          // k 0-15
        mma16816(c, a + 4, b + 2);  // k 16-31

        __nv_bfloat162 p01 = __float22bfloat162_rn(make_float2(c[0], c[1]));
        __nv_bfloat162 p23 = __float22bfloat162_rn(make_float2(c[2], c[3]));
        const int row = warp * 16 + (lane >> 2);
        const int colb = (8 * j + 2 * (lane & 3)) * 2;   // byte col
        *(__nv_bfloat162*)(sO + row * OSTR + colb) = p01;
        *(__nv_bfloat162*)(sO + (row + 8) * OSTR + colb) = p23;
    }
    __syncthreads();

    // ---- coalesced copy-out: 128 rows x 128 B payload -> g_U ----
    char* __restrict__ gU = (char*)g_U;
    #pragma unroll
    for (int i = 0; i < 4; ++i) {
        const int idx = tid + 256 * i;           // 1024 uint4 total
        const int row = idx >> 3, ch = idx & 7;
        const uint4 v = *(const uint4*)(sO + row * OSTR + ch * 16);
        *(uint4*)(gU + (size_t)(m0 + row) * (NCOL * 2) + n0 * 2 + ch * 16) = v;
    }
}

// ---------------------------------------------------------------- attention
constexpr int AW = 8;   // warps (batch elems) per attn block

__global__ void __launch_bounds__(256) attn_kernel(
    const int* __restrict__ mem_h,
    const int* __restrict__ mem_r,
    const int* __restrict__ mem_t,
    const int* __restrict__ users,
    const float* __restrict__ entity,
    const float* __restrict__ user_table,
    float* __restrict__ out,
    int hop, int last)
{
    __shared__ float P[AW][N_MEM * 9];

    const int lane = threadIdx.x & 31;
    const int warp = threadIdx.x >> 5;
    const int b = blockIdx.x * AW + warp;
    float* __restrict__ Pw = P[warp];

    const int base = hop * BATCH * N_MEM + b * N_MEM;
    const int hidx = mem_h[base + lane];
    const int ridx = mem_r[base + lane];
    const int tidx = mem_t[base + lane];

    const float item = g_item[b * DIM + lane];

    // ---- partial dots: 4 memories/iter, 8 lanes each (e = 4c..4c+3) ----
    const int mq = lane >> 3;
    const int c  = lane & 7;
    const __nv_bfloat16* __restrict__ Ub = g_U + (size_t)b * NCOL;

    #pragma unroll
    for (int it = 0; it < 8; ++it) {
        const int m = it * 4 + mq;
        const int r_i = __shfl_sync(FULL, ridx, m);
        const int h_i = __shfl_sync(FULL, hidx, m);
        const uint2 uu = *(const uint2*)(Ub + r_i * DIM + 4 * c);  // 4 bf16
        const float4 h4 = *(const float4*)(entity + h_i * DIM + 4 * c);
        Pw[m * 9 + c] = bf_lo(uu.x) * h4.x + bf_hi(uu.x) * h4.y +
                        bf_lo(uu.y) * h4.z + bf_hi(uu.y) * h4.w;
    }
    __syncwarp();

    // ---- logit[m] (lane m) = sum of 8 partials ----
    float logit = 0.f;
    #pragma unroll
    for (int j = 0; j < 8; ++j) logit += Pw[lane * 9 + j];

    // ---- softmax ----
    float mx = logit;
    #pragma unroll
    for (int off = 16; off; off >>= 1)
        mx = fmaxf(mx, __shfl_xor_sync(FULL, mx, off));
    const float ex = __expf(logit - mx);
    float denom = ex;
    #pragma unroll
    for (int off = 16; off; off >>= 1)
        denom += __shfl_xor_sync(FULL, denom, off);
    const float prob = ex / denom;

    // ---- o[d] = sum_m prob[m] * t_m[d] ----
    float o = 0.f;
    #pragma unroll 4
    for (int m = 0; m < N_MEM; ++m) {
        const int t_i = __shfl_sync(FULL, tidx, m);
        const float p = __shfl_sync(FULL, prob, m);
        o = fmaf(p, entity[t_i * DIM + lane], o);
    }

    // ---- item' = (item + o) @ W^T ----
    const float tmp = item + o;
    float itn = 0.f;
    #pragma unroll
    for (int e = 0; e < DIM; ++e)
        itn = fmaf(__shfl_sync(FULL, tmp, e), g_Wt[e * DIM + lane], itn);

    if (!last) {
        g_item[b * DIM + lane] = itn;
        g_item_bf[b * DIM + lane] = __float2bfloat16(itn);
        g_y[b * DIM + lane] = o;
    } else {
        const float y = g_y[b * DIM + lane] + o
                      + user_table[users[b] * DIM + lane];
        float s = itn * y;
        #pragma unroll
        for (int off = 16; off; off >>= 1)
            s += __shfl_xor_sync(FULL, s, off);
        if (lane == 0)
            out[b] = 1.f / (1.f + __expf(-s));
    }
}

// ---------------------------------------------------------------- launch
extern "C" void kernel_launch(void* const* d_in, const int* in_sizes, int n_in,
                              void* d_out, int out_size) {
    const int*   items     = (const int*)d_in[0];
    const int*   mem_h     = (const int*)d_in[2];
    const int*   mem_r     = (const int*)d_in[3];
    const int*   mem_t     = (const int*)d_in[4];
    const int*   users     = (const int*)d_in[5];
    const float* entity    = (const float*)d_in[6];
    const float* relation  = (const float*)d_in[7];
    const float* user_tab  = (const float*)d_in[8];
    const float* W         = (const float*)d_in[9];
    float* out = (float*)d_out;

    prep_kernel<<<(BATCH * DIM + 255) / 256, 256>>>(items, entity, relation, W);

    const dim3 ggrid(NCOL / GN, BATCH / GM);   // 32 x 32
    gemm_kernel<<<ggrid, 256>>>();
    attn_kernel<<<BATCH / AW, 256>>>(mem_h, mem_r, mem_t, users,
                                     entity, user_tab, out, 0, 0);
    gemm_kernel<<<ggrid, 256>>>();
    attn_kernel<<<BATCH / AW, 256>>>(mem_h, mem_r, mem_t, users,
                                     entity, user_tab, out, 1, 1);
}